// round 14
// baseline (speedup 1.0000x reference)
#include <cuda_runtime.h>
#include <cuda_bf16.h>
#include <cstdint>

#define B_ 32
#define S_ 2048
#define H_ 1024
#define L_ 32
#define NCH 32             // scan chunks per batch (64 steps each)
#define CSTEPS (S_ / NCH)  // 64
#define KC  32             // GEMM K-chunk
#define NKC (H_ / KC)      // 32 K-chunks
#define NSEG 16            // numerator segments
#define LN2D 0.6931471805599453

// scratch (no device allocs allowed)
__device__ float g_av[B_][NCH - 1][L_];
__device__ int   g_aez[B_][NCH - 1];
__device__ float g_bv[B_][NCH][L_];
__device__ int   g_bez[B_][NCH];
__device__ float g_num_part[B_][NSEG];
__device__ int   g_msum_part[B_][NSEG];
__device__ float g_llh[B_];
__device__ int   g_count = 0;   // release counter: scan+num blocks done
__device__ int   g_done  = 0;   // final blocks done
// W in mma.sync B-fragment order: [term(hi/lo)][kc][s][g][lane][reg] bf16x2
__device__ __align__(16) unsigned int g_Wf[2 * NKC * 512];

// ---- packed f32x2 helpers (scan) --------------------------------------------
__device__ __forceinline__ unsigned long long ffma2(unsigned long long a,
                                                    unsigned long long b,
                                                    unsigned long long c) {
    unsigned long long d;
    asm("fma.rn.f32x2 %0, %1, %2, %3;" : "=l"(d) : "l"(a), "l"(b), "l"(c));
    return d;
}
__device__ __forceinline__ unsigned long long fadd2(unsigned long long a,
                                                    unsigned long long b) {
    unsigned long long d;
    asm("add.rn.f32x2 %0, %1, %2;" : "=l"(d) : "l"(a), "l"(b));
    return d;
}
__device__ __forceinline__ unsigned long long fpack2(float lo, float hi) {
    unsigned long long d;
    asm("mov.b64 %0, {%1, %2};" : "=l"(d) : "f"(lo), "f"(hi));
    return d;
}
__device__ __forceinline__ float funpack_add(unsigned long long a) {
    float lo, hi;
    asm("mov.b64 {%0, %1}, %2;" : "=f"(lo), "=f"(hi) : "l"(a));
    return lo + hi;
}

// ---- cp.async ----------------------------------------------------------------
__device__ __forceinline__ void cp_async16(unsigned int dst, const void* src) {
    asm volatile("cp.async.cg.shared.global [%0], [%1], 16;" :: "r"(dst), "l"(src));
}
__device__ __forceinline__ void cp_commit() {
    asm volatile("cp.async.commit_group;");
}
template <int N>
__device__ __forceinline__ void cp_wait() {
    asm volatile("cp.async.wait_group %0;" :: "n"(N));
}

// ---- bf16 helpers -------------------------------------------------------------
__device__ __forceinline__ unsigned int bfpack(float x, float y) {
    unsigned int r;
    asm("cvt.rn.bf16x2.f32 %0, %1, %2;" : "=r"(r) : "f"(y), "f"(x));
    return r;
}
__device__ __forceinline__ void bfsplit(float x, float y,
                                        unsigned int& hi, unsigned int& lo) {
    unsigned int h = bfpack(x, y);
    float hx = __int_as_float(h << 16);
    float hy = __int_as_float(h & 0xffff0000u);
    hi = h;
    lo = bfpack(x - hx, y - hy);
}

// ---- mma.sync bf16 (m16n8k16, row.col, f32 acc) -------------------------------
__device__ __forceinline__ void mma_bf16(float* d, const unsigned int* a,
                                         const unsigned int* b) {
    asm volatile(
        "mma.sync.aligned.m16n8k16.row.col.f32.bf16.bf16.f32 "
        "{%0,%1,%2,%3}, {%4,%5,%6,%7}, {%8,%9}, {%0,%1,%2,%3};"
        : "+f"(d[0]), "+f"(d[1]), "+f"(d[2]), "+f"(d[3])
        : "r"(a[0]), "r"(a[1]), "r"(a[2]), "r"(a[3]), "r"(b[0]), "r"(b[1]));
}

// ---------------------------------------------------------------------------
// Kernel 0: W -> bf16 hi/lo B-fragments (KC=32).
// ---------------------------------------------------------------------------
__global__ void wfrag_kernel(const float* __restrict__ W) {
    int i = blockIdx.x * blockDim.x + threadIdx.x;   // 0 .. 32767
    int r  = i & 1;
    int l  = (i >> 1) & 31;
    int g  = (i >> 6) & 3;
    int s  = (i >> 8) & 1;
    int kc = (i >> 9) & 31;
    int t  = (i >> 14) & 1;
    int k  = kc * KC + s * 16 + (l & 3) * 2 + r * 8;
    int n  = g * 8 + (l >> 2);
    float w0 = W[k * L_ + n];
    float w1 = W[(k + 1) * L_ + n];
    unsigned int hi, lo;
    bfsplit(w0, w1, hi, lo);
    g_Wf[i] = t ? lo : hi;
}

// ---------------------------------------------------------------------------
// Kernel 1: logits = hidden @ W + b via mma.sync bf16-split, KC=32,
// 64-row tiles, grid 1024, 7 CTAs/SM (exact round-12 form, 86.0us baseline).
// ---------------------------------------------------------------------------
#define HB_OFF 0u
#define WB_OFF 16384u
#define SMEM_TOTAL_G (16384 + 3 * 4096)

__global__ __launch_bounds__(128, 7) void gemm_mma_kernel(
    const float* __restrict__ hidden,
    const float* __restrict__ bias,
    float* __restrict__ out)
{
    extern __shared__ __align__(16) char smem[];
    const unsigned int sbase = (unsigned int)__cvta_generic_to_shared(smem);
    const int tid  = threadIdx.x;
    const int wid  = tid >> 5;
    const int lane = tid & 31;
    const size_t R0 = (size_t)blockIdx.x * 64;

    auto stageH = [&](int kc, int slot) {
#pragma unroll
        for (int p = 0; p < 4; p++) {
            int idx = p * 128 + tid;
            int row = idx >> 3;
            int c16 = idx & 7;
            const float* src = hidden + (R0 + row) * H_ + kc * KC + c16 * 4;
            unsigned int dst = sbase + HB_OFF + (unsigned int)slot * 8192u
                + (unsigned int)(row * 128 + (((c16 >> 1) ^ (row & 3)) << 5)
                                 + (c16 & 1) * 16);
            cp_async16(dst, src);
        }
    };
    auto stageW = [&](int kc, int slot) {
#pragma unroll
        for (int i = 0; i < 2; i++) {
            int idx = tid + 128 * i;
            int t   = idx >> 7;
            int off = idx & 127;
            const char* src = (const char*)g_Wf + (t * NKC + kc) * 2048 + off * 16;
            unsigned int dst = sbase + WB_OFF + (unsigned int)slot * 4096u
                + (unsigned int)(t * 2048 + off * 16);
            cp_async16(dst, src);
        }
    };

    float acc[4][4];
#pragma unroll
    for (int g = 0; g < 4; g++)
#pragma unroll
        for (int r = 0; r < 4; r++) acc[g][r] = 0.f;

    stageH(0, 0); stageW(0, 0); cp_commit();

    const int r0 = wid * 16 + (lane >> 2);
    const int r1 = r0 + 8;
    const int co = (lane & 3) * 2;

    for (int kc = 0; kc < NKC; kc++) {
        const int hs = kc & 1;
        const int wslot = kc % 3;
        if (kc + 1 < NKC) {
            stageH(kc + 1, hs ^ 1);
            stageW(kc + 1, (kc + 1) % 3);
            cp_commit();
            cp_wait<1>();
        } else {
            cp_wait<0>();
        }
        __syncthreads();

        const float* hb = (const float*)(smem + HB_OFF + hs * 8192);
        const unsigned int* wb = (const unsigned int*)(smem + WB_OFF + wslot * 4096);

#pragma unroll
        for (int s = 0; s < 2; s++) {
            const int cc0 = 2 * s, cc1 = 2 * s + 1;
            float2 p00 = *(const float2*)(hb + r0 * 32 + ((cc0 ^ (r0 & 3)) << 3) + co);
            float2 p10 = *(const float2*)(hb + r1 * 32 + ((cc0 ^ (r1 & 3)) << 3) + co);
            float2 p01 = *(const float2*)(hb + r0 * 32 + ((cc1 ^ (r0 & 3)) << 3) + co);
            float2 p11 = *(const float2*)(hb + r1 * 32 + ((cc1 ^ (r1 & 3)) << 3) + co);
            unsigned int ahi[4], alo[4];
            bfsplit(p00.x, p00.y, ahi[0], alo[0]);
            bfsplit(p10.x, p10.y, ahi[1], alo[1]);
            bfsplit(p01.x, p01.y, ahi[2], alo[2]);
            bfsplit(p11.x, p11.y, ahi[3], alo[3]);
#pragma unroll
            for (int g = 0; g < 4; g++) {
                uint2 bh = *(const uint2*)(wb + ((s * 4 + g) * 32 + lane) * 2);
                uint2 bl = *(const uint2*)(wb + 512 + ((s * 4 + g) * 32 + lane) * 2);
                unsigned int bhr[2] = { bh.x, bh.y };
                unsigned int blr[2] = { bl.x, bl.y };
                mma_bf16(acc[g], ahi, bhr);
                mma_bf16(acc[g], ahi, blr);
                mma_bf16(acc[g], alo, bhr);
            }
        }
        __syncthreads();
    }

#pragma unroll
    for (int g = 0; g < 4; g++) {
        int cbase = g * 8 + co;
        float b0 = bias[cbase];
        float b1 = bias[cbase + 1];
        float* p = out + (R0 + r0) * L_ + cbase;
        float* q = out + (R0 + r1) * L_ + cbase;
        p[0] = acc[g][0] + b0;
        p[1] = acc[g][1] + b1;
        q[0] = acc[g][2] + b0;
        q[1] = acc[g][3] + b1;
    }
}

// ---------------------------------------------------------------------------
// Kernel 2: fused chunk-scans + numerator + (tail blocks) final combine.
// blocks [0, SCAN_BLOCKS): 4 scan warp-jobs per block.
// blocks [SCAN_BLOCKS, SCAN_BLOCKS + B_*NSEG): numerator segments.
// blocks [SCAN_BLOCKS + B_*NSEG, +B_): final combine for batch b
//   (spin on g_count release counter — threadFenceReduction pattern).
// ---------------------------------------------------------------------------
#define SCAN_JOBS (2 * (NCH - 1))                 // 62
#define SCAN_BLOCKS (SCAN_JOBS * B_ / 4)          // 496
#define WORK_BLOCKS (SCAN_BLOCKS + B_ * NSEG)     // 1008
#define NJOBF (2 * NCH - 3)                       // 61

__global__ __launch_bounds__(128) void scannum_kernel(
    const float* __restrict__ logits,
    const int*   __restrict__ mask,
    const float* __restrict__ trans,
    const float* __restrict__ start,
    const float* __restrict__ endt,
    const int*   __restrict__ labels,
    float* __restrict__ loss_out)
{
    __shared__ __align__(16) float buf4[4][2][L_];
    __shared__ float sp[4];
    __shared__ int   sm_[4];
    __shared__ double shd[64];
    __shared__ int   is_last;

    const int tid  = threadIdx.x;
    const int w    = tid >> 5;
    const int lane = tid & 31;

    if (blockIdx.x < SCAN_BLOCKS) {
        // ---- scan path ----
        const int gj  = blockIdx.x * 4 + w;
        const int b   = gj / SCAN_JOBS;
        const int job = gj % SCAN_JOBS;
        const int dir = (job < NCH - 1) ? 0 : 1;
        const int c   = (job < NCH - 1) ? job : (job - NCH + 2);
        const int j   = lane;
        const float* lg = logits + (size_t)b * S_ * L_;
        const int*   mk = mask + (size_t)b * S_;
        float (*buf)[L_] = buf4[w];

        const int t0 = (c == 0) ? 1 : CSTEPS * c;
        const int t1 = CSTEPS * (c + 1);
        const int nlive = t1 - t0;

        unsigned long long etp[16];
        if (dir == 0) {
#pragma unroll
            for (int u = 0; u < 16; u++)
                etp[u] = fpack2(__expf(trans[(2 * u) * L_ + j]),
                                __expf(trans[(2 * u + 1) * L_ + j]));
        } else {
#pragma unroll
            for (int u = 0; u < 16; u++)
                etp[u] = fpack2(__expf(trans[j * L_ + 2 * u]),
                                __expf(trans[j * L_ + 2 * u + 1]));
        }

        float A;
        if (dir == 0) A = (c == 0)       ? __expf(start[j] + lg[j]) : 1.0f;
        else          A = (c == NCH - 1) ? __expf(endt[j])          : 1.0f;
        int ez = 0;
        int p  = 0;

        float emb[8];
        int   mb[8];
#pragma unroll
        for (int u = 0; u < 8; u++) {
            int t = (dir == 0) ? (t0 + u) : (t1 - 1 - u);
            emb[u] = __expf(lg[(size_t)t * L_ + j]);
            mb[u]  = mk[t];
        }

        for (int blk = 0; blk < CSTEPS / 8; blk++) {
#pragma unroll
            for (int u = 0; u < 8; u++) {
                const int s = blk * 8 + u;
                float x = (dir == 0) ? A : A * emb[u];
                buf[p][j] = x;
                __syncwarp();
                const ulonglong2* bp = reinterpret_cast<const ulonglong2*>(buf[p]);
                unsigned long long a0 = 0ull, a1 = 0ull, a2 = 0ull, a3 = 0ull;
                ulonglong2 v00 = bp[0];
#pragma unroll
                for (int q = 0; q < 4; q++) {
                    ulonglong2 v0 = (q == 0) ? v00 : bp[q * 2];
                    ulonglong2 v1 = bp[q * 2 + 1];
                    a0 = ffma2(v0.x, etp[q * 4 + 0], a0);
                    a1 = ffma2(v0.y, etp[q * 4 + 1], a1);
                    a2 = ffma2(v1.x, etp[q * 4 + 2], a2);
                    a3 = ffma2(v1.y, etp[q * 4 + 3], a3);
                }
                float dot  = funpack_add(fadd2(fadd2(a0, a1), fadd2(a2, a3)));
                float Anew = (dir == 0) ? dot * emb[u] : dot;
                bool live  = (s < nlive);
                A = (mb[u] && live) ? Anew : A;

                if (u == 7) {
                    float a0f;
                    asm("mov.b64 {%0, _}, %1;" : "=f"(a0f) : "l"(v00.x));
                    a0f = fmaxf(a0f, 1e-30f);
                    int sb = (__float_as_int(a0f) >> 23) & 0xff;
                    A  *= __int_as_float((254 - sb) << 23);
                    ez += sb - 127;
                }
                p ^= 1;
                // prefetch 8 ahead: fwd <= 1992 < S_, bwd >= 56 >= 0
                int tn = (dir == 0) ? (t0 + s + 9) : (t1 - 9 - s);
                emb[u] = __expf(lg[(size_t)tn * L_ + j]);
                mb[u]  = mk[tn];
            }
        }

        buf[p][j] = A;
        __syncwarp();
        float a0f = fmaxf(buf[p][0], 1e-30f);
        int   sb = (__float_as_int(a0f) >> 23) & 0xff;
        A  *= __int_as_float((254 - sb) << 23);
        ez += sb - 127;
        if (dir == 0) { g_av[b][c][j] = A; if (j == 0) g_aez[b][c] = ez; }
        else          { g_bv[b][c][j] = A; if (j == 0) g_bez[b][c] = ez; }

        // release
        __syncthreads();
        if (tid == 0) { __threadfence(); atomicAdd(&g_count, 1); }
    } else if (blockIdx.x < WORK_BLOCKS) {
        // ---- numerator path ----
        const int nb  = blockIdx.x - SCAN_BLOCKS;
        const int b   = nb >> 4;
        const int seg = nb & 15;
        const int*   lb = labels + (size_t)b * S_;
        const int*   mk = mask + (size_t)b * S_;
        const float* lg = logits + (size_t)b * S_ * L_;

        float part = 0.f;
        int   msum = 0;
        int   t    = seg * 128 + tid;
        msum += (mk[t] > 0);
        if (t >= 1 && mk[t] > 0) {
            int cur = lb[t], prev = lb[t - 1];
            part += lg[(size_t)t * L_ + cur] + trans[prev * L_ + cur];
        }
#pragma unroll
        for (int off = 16; off > 0; off >>= 1) {
            part += __shfl_xor_sync(0xffffffffu, part, off);
            msum += __shfl_xor_sync(0xffffffffu, msum, off);
        }
        if (lane == 0) { sp[w] = part; sm_[w] = msum; }
        __syncthreads();
        if (tid == 0) {
            float ps = 0.f; int ms = 0;
#pragma unroll
            for (int i = 0; i < 4; i++) { ps += sp[i]; ms += sm_[i]; }
            g_num_part[b][seg]  = ps;
            g_msum_part[b][seg] = ms;
            __threadfence();
            atomicAdd(&g_count, 1);
        }
    } else {
        // ---- final combine for batch b (after all scan/num blocks release) ----
        const int b = blockIdx.x - WORK_BLOCKS;
        if (tid == 0) {
            while (atomicAdd(&g_count, 0) < WORK_BLOCKS) __nanosleep(64);
        }
        __syncthreads();
        __threadfence();

        // 61 boundary jobs over 4 warps
#pragma unroll
        for (int jj = 0; jj < 16; jj++) {
            int job = w * 16 + jj;
            if (job < NJOBF) {
                double val;
                if (job < NCH - 1) {
                    int c = job;
                    float d = g_av[b][c][lane] * g_bv[b][c + 1][lane];
#pragma unroll
                    for (int off = 16; off > 0; off >>= 1)
                        d += __shfl_xor_sync(0xffffffffu, d, off);
                    val = (double)__logf(d)
                        + (double)(g_aez[b][c] + g_bez[b][c + 1]) * LN2D;
                } else {
                    int c = job - NCH + 2;
                    float sm = g_bv[b][c][lane];
#pragma unroll
                    for (int off = 16; off > 0; off >>= 1)
                        sm += __shfl_xor_sync(0xffffffffu, sm, off);
                    val = -((double)__logf(sm) + (double)g_bez[b][c] * LN2D);
                }
                if (lane == 0) shd[job] = val;
            }
        }
        __syncthreads();

        if (w == 0) {
            double v = (lane < NJOBF) ? shd[lane] : 0.0;
            if (lane + 32 < NJOBF) v += shd[lane + 32];
#pragma unroll
            for (int off = 16; off > 0; off >>= 1)
                v += __shfl_xor_sync(0xffffffffu, v, off);
            if (lane == 0) {
                float part = 0.f; int m = 0;
#pragma unroll
                for (int i = 0; i < NSEG; i++) {
                    part += g_num_part[b][i];
                    m    += g_msum_part[b][i];
                }
                const int*   lb = labels + (size_t)b * S_;
                const float* lg = logits + (size_t)b * S_ * L_;
                int first = lb[0];
                int last  = lb[m - 1];
                float num = start[first] + lg[first] + part + endt[last];
                g_llh[b] = num - (float)v;
                __threadfence();
                int prev = atomicAdd(&g_done, 1);
                is_last = (prev == B_ - 1) ? 1 : 0;
            }
        }
        __syncthreads();

        if (is_last && w == 0) {
            __threadfence();
            float v = g_llh[lane];
#pragma unroll
            for (int off = 16; off > 0; off >>= 1)
                v += __shfl_xor_sync(0xffffffffu, v, off);
            if (lane == 0) {
                loss_out[0] = -(v * (1.0f / B_));
                g_done  = 0;   // reset for next graph replay
                g_count = 0;
                __threadfence();
            }
        }
    }
}

// ---------------------------------------------------------------------------
extern "C" void kernel_launch(void* const* d_in, const int* in_sizes, int n_in,
                              void* d_out, int out_size)
{
    const float* hidden = (const float*)d_in[0];
    const float* W      = (const float*)d_in[1];
    const float* bias   = (const float*)d_in[2];
    const float* trans  = (const float*)d_in[3];
    const float* start  = (const float*)d_in[4];
    const float* endt   = (const float*)d_in[5];
    const int*   labels = (const int*)d_in[6];
    const int*   mask   = (const int*)d_in[7];

    float* out    = (float*)d_out;
    float* logits = out + 1;   // d_out = [loss, logits...]

    cudaFuncSetAttribute(gemm_mma_kernel, cudaFuncAttributeMaxDynamicSharedMemorySize, SMEM_TOTAL_G);

    wfrag_kernel<<<128, 256>>>(W);
    gemm_mma_kernel<<<(B_ * S_) / 64, 128, SMEM_TOTAL_G>>>(hidden, bias, logits);
    scannum_kernel<<<WORK_BLOCKS + B_, 128>>>(logits, mask, trans, start, endt, labels, out);
}

// round 15
// speedup vs baseline: 1.0831x; 1.0831x over previous
#include <cuda_runtime.h>
#include <cuda_bf16.h>
#include <cstdint>

#define B_ 32
#define S_ 2048
#define H_ 1024
#define L_ 32
#define NCH 32             // scan chunks per batch (64 steps each)
#define CSTEPS (S_ / NCH)  // 64
#define KC  32             // GEMM K-chunk
#define NKC (H_ / KC)      // 32 K-chunks
#define NSEG 16            // numerator segments
#define LN2D 0.6931471805599453

// scratch (no device allocs allowed)
__device__ float g_av[B_][NCH - 1][L_];
__device__ int   g_aez[B_][NCH - 1];
__device__ float g_bv[B_][NCH][L_];
__device__ int   g_bez[B_][NCH];
__device__ float g_num_part[B_][NSEG];
__device__ int   g_msum_part[B_][NSEG];
__device__ float g_llh[B_];
__device__ int   g_done = 0;
// W in mma.sync B-fragment order: [term(hi/lo)][kc][s][g][lane][reg] bf16x2
__device__ __align__(16) unsigned int g_Wf[2 * NKC * 512];

// ---- packed f32x2 helpers (scan) --------------------------------------------
__device__ __forceinline__ unsigned long long ffma2(unsigned long long a,
                                                    unsigned long long b,
                                                    unsigned long long c) {
    unsigned long long d;
    asm("fma.rn.f32x2 %0, %1, %2, %3;" : "=l"(d) : "l"(a), "l"(b), "l"(c));
    return d;
}
__device__ __forceinline__ unsigned long long fadd2(unsigned long long a,
                                                    unsigned long long b) {
    unsigned long long d;
    asm("add.rn.f32x2 %0, %1, %2;" : "=l"(d) : "l"(a), "l"(b));
    return d;
}
__device__ __forceinline__ unsigned long long fpack2(float lo, float hi) {
    unsigned long long d;
    asm("mov.b64 %0, {%1, %2};" : "=l"(d) : "f"(lo), "f"(hi));
    return d;
}
__device__ __forceinline__ float funpack_add(unsigned long long a) {
    float lo, hi;
    asm("mov.b64 {%0, %1}, %2;" : "=f"(lo), "=f"(hi) : "l"(a));
    return lo + hi;
}

// ---- cp.async ----------------------------------------------------------------
__device__ __forceinline__ void cp_async16(unsigned int dst, const void* src) {
    asm volatile("cp.async.cg.shared.global [%0], [%1], 16;" :: "r"(dst), "l"(src));
}
__device__ __forceinline__ void cp_commit() {
    asm volatile("cp.async.commit_group;");
}
template <int N>
__device__ __forceinline__ void cp_wait() {
    asm volatile("cp.async.wait_group %0;" :: "n"(N));
}

// ---- bf16 helpers -------------------------------------------------------------
__device__ __forceinline__ unsigned int bfpack(float x, float y) {
    unsigned int r;
    asm("cvt.rn.bf16x2.f32 %0, %1, %2;" : "=r"(r) : "f"(y), "f"(x));
    return r;
}
__device__ __forceinline__ void bfsplit(float x, float y,
                                        unsigned int& hi, unsigned int& lo) {
    unsigned int h = bfpack(x, y);
    float hx = __int_as_float(h << 16);
    float hy = __int_as_float(h & 0xffff0000u);
    hi = h;
    lo = bfpack(x - hx, y - hy);
}

// ---- mma.sync bf16 (m16n8k16, row.col, f32 acc) -------------------------------
__device__ __forceinline__ void mma_bf16(float* d, const unsigned int* a,
                                         const unsigned int* b) {
    asm volatile(
        "mma.sync.aligned.m16n8k16.row.col.f32.bf16.bf16.f32 "
        "{%0,%1,%2,%3}, {%4,%5,%6,%7}, {%8,%9}, {%0,%1,%2,%3};"
        : "+f"(d[0]), "+f"(d[1]), "+f"(d[2]), "+f"(d[3])
        : "r"(a[0]), "r"(a[1]), "r"(a[2]), "r"(a[3]), "r"(b[0]), "r"(b[1]));
}

// ---------------------------------------------------------------------------
// Kernel 0: W -> bf16 hi/lo B-fragments (KC=32), read-coalesced.
// Thread handles one k-pair (k0, k0+1) for one n: reads two 128B-contiguous
// rows per warp; writes hi/lo fragment words.
// frag index: i = ((((t*NKC + kc)*2 + s)*4 + g)*32 + l)*2 + r
//   k = kc*32 + s*16 + r*8 + (l&3)*2 + {0,1},  n = g*8 + (l>>2)
// ---------------------------------------------------------------------------
__global__ void wfrag_kernel(const float* __restrict__ W) {
    int idx = blockIdx.x * blockDim.x + threadIdx.x;   // 0 .. 16383
    int n   = idx & 31;
    int kp  = idx >> 5;         // k-pair index, k0 = 2*kp
    int k0  = kp * 2;
    float w0 = W[k0 * L_ + n];
    float w1 = W[(k0 + 1) * L_ + n];
    unsigned int hi, lo;
    bfsplit(w0, w1, hi, lo);
    int kc = k0 >> 5;
    int s  = (k0 >> 4) & 1;
    int r  = (k0 >> 3) & 1;
    int l  = (n & 7) * 4 + ((k0 >> 1) & 3);
    int g  = n >> 3;
    int base = ((((kc) * 2 + s) * 4 + g) * 32 + l) * 2 + r;
    g_Wf[base] = hi;                       // t=0
    g_Wf[base + NKC * 512] = lo;           // t=1
}

// ---------------------------------------------------------------------------
// Kernel 1: logits = hidden @ W + b via mma.sync bf16-split, KC=32,
// 64-row tiles, grid 1024, 7 CTAs/SM (round-12 form, 86.0us baseline).
// ---------------------------------------------------------------------------
#define HB_OFF 0u
#define WB_OFF 16384u
#define SMEM_TOTAL_G (16384 + 3 * 4096)

__global__ __launch_bounds__(128, 7) void gemm_mma_kernel(
    const float* __restrict__ hidden,
    const float* __restrict__ bias,
    float* __restrict__ out)
{
    extern __shared__ __align__(16) char smem[];
    const unsigned int sbase = (unsigned int)__cvta_generic_to_shared(smem);
    const int tid  = threadIdx.x;
    const int wid  = tid >> 5;
    const int lane = tid & 31;
    const size_t R0 = (size_t)blockIdx.x * 64;

    auto stageH = [&](int kc, int slot) {
#pragma unroll
        for (int p = 0; p < 4; p++) {
            int idx = p * 128 + tid;
            int row = idx >> 3;
            int c16 = idx & 7;
            const float* src = hidden + (R0 + row) * H_ + kc * KC + c16 * 4;
            unsigned int dst = sbase + HB_OFF + (unsigned int)slot * 8192u
                + (unsigned int)(row * 128 + (((c16 >> 1) ^ (row & 3)) << 5)
                                 + (c16 & 1) * 16);
            cp_async16(dst, src);
        }
    };
    auto stageW = [&](int kc, int slot) {
#pragma unroll
        for (int i = 0; i < 2; i++) {
            int idx = tid + 128 * i;
            int t   = idx >> 7;
            int off = idx & 127;
            const char* src = (const char*)g_Wf + (t * NKC + kc) * 2048 + off * 16;
            unsigned int dst = sbase + WB_OFF + (unsigned int)slot * 4096u
                + (unsigned int)(t * 2048 + off * 16);
            cp_async16(dst, src);
        }
    };

    float acc[4][4];
#pragma unroll
    for (int g = 0; g < 4; g++)
#pragma unroll
        for (int r = 0; r < 4; r++) acc[g][r] = 0.f;

    stageH(0, 0); stageW(0, 0); cp_commit();

    const int r0 = wid * 16 + (lane >> 2);
    const int r1 = r0 + 8;
    const int co = (lane & 3) * 2;

    for (int kc = 0; kc < NKC; kc++) {
        const int hs = kc & 1;
        const int wslot = kc % 3;
        if (kc + 1 < NKC) {
            stageH(kc + 1, hs ^ 1);
            stageW(kc + 1, (kc + 1) % 3);
            cp_commit();
            cp_wait<1>();
        } else {
            cp_wait<0>();
        }
        __syncthreads();

        const float* hb = (const float*)(smem + HB_OFF + hs * 8192);
        const unsigned int* wb = (const unsigned int*)(smem + WB_OFF + wslot * 4096);

#pragma unroll
        for (int s = 0; s < 2; s++) {
            const int cc0 = 2 * s, cc1 = 2 * s + 1;
            float2 p00 = *(const float2*)(hb + r0 * 32 + ((cc0 ^ (r0 & 3)) << 3) + co);
            float2 p10 = *(const float2*)(hb + r1 * 32 + ((cc0 ^ (r1 & 3)) << 3) + co);
            float2 p01 = *(const float2*)(hb + r0 * 32 + ((cc1 ^ (r0 & 3)) << 3) + co);
            float2 p11 = *(const float2*)(hb + r1 * 32 + ((cc1 ^ (r1 & 3)) << 3) + co);
            unsigned int ahi[4], alo[4];
            bfsplit(p00.x, p00.y, ahi[0], alo[0]);
            bfsplit(p10.x, p10.y, ahi[1], alo[1]);
            bfsplit(p01.x, p01.y, ahi[2], alo[2]);
            bfsplit(p11.x, p11.y, ahi[3], alo[3]);
#pragma unroll
            for (int g = 0; g < 4; g++) {
                uint2 bh = *(const uint2*)(wb + ((s * 4 + g) * 32 + lane) * 2);
                uint2 bl = *(const uint2*)(wb + 512 + ((s * 4 + g) * 32 + lane) * 2);
                unsigned int bhr[2] = { bh.x, bh.y };
                unsigned int blr[2] = { bl.x, bl.y };
                mma_bf16(acc[g], ahi, bhr);
                mma_bf16(acc[g], ahi, blr);
                mma_bf16(acc[g], alo, bhr);
            }
        }
        __syncthreads();
    }

#pragma unroll
    for (int g = 0; g < 4; g++) {
        int cbase = g * 8 + co;
        float b0 = bias[cbase];
        float b1 = bias[cbase + 1];
        float* p = out + (R0 + r0) * L_ + cbase;
        float* q = out + (R0 + r1) * L_ + cbase;
        p[0] = acc[g][0] + b0;
        p[1] = acc[g][1] + b1;
        q[0] = acc[g][2] + b0;
        q[1] = acc[g][3] + b1;
    }
}

// ---------------------------------------------------------------------------
// Kernel 2: fused chunk-scans + numerator partials (round-12 form,
// fwd prefetch ring FIXED: tn = t0 + s + 8).
// ---------------------------------------------------------------------------
#define SCAN_JOBS (2 * (NCH - 1))                 // 62
#define SCAN_BLOCKS (SCAN_JOBS * B_ / 4)          // 496

__global__ __launch_bounds__(128) void scannum_kernel(
    const float* __restrict__ logits,
    const int*   __restrict__ mask,
    const float* __restrict__ trans,
    const float* __restrict__ start,
    const float* __restrict__ endt,
    const int*   __restrict__ labels)
{
    __shared__ __align__(16) float buf4[4][2][L_];
    __shared__ float sp[4];
    __shared__ int   sm_[4];

    const int tid  = threadIdx.x;
    const int w    = tid >> 5;
    const int lane = tid & 31;

    if (blockIdx.x < SCAN_BLOCKS) {
        const int gj  = blockIdx.x * 4 + w;
        const int b   = gj / SCAN_JOBS;
        const int job = gj % SCAN_JOBS;
        const int dir = (job < NCH - 1) ? 0 : 1;
        const int c   = (job < NCH - 1) ? job : (job - NCH + 2);
        const int j   = lane;
        const float* lg = logits + (size_t)b * S_ * L_;
        const int*   mk = mask + (size_t)b * S_;
        float (*buf)[L_] = buf4[w];

        const int t0 = (c == 0) ? 1 : CSTEPS * c;
        const int t1 = CSTEPS * (c + 1);
        const int nlive = t1 - t0;

        unsigned long long etp[16];
        if (dir == 0) {
#pragma unroll
            for (int u = 0; u < 16; u++)
                etp[u] = fpack2(__expf(trans[(2 * u) * L_ + j]),
                                __expf(trans[(2 * u + 1) * L_ + j]));
        } else {
#pragma unroll
            for (int u = 0; u < 16; u++)
                etp[u] = fpack2(__expf(trans[j * L_ + 2 * u]),
                                __expf(trans[j * L_ + 2 * u + 1]));
        }

        float A;
        if (dir == 0) A = (c == 0)       ? __expf(start[j] + lg[j]) : 1.0f;
        else          A = (c == NCH - 1) ? __expf(endt[j])          : 1.0f;
        int ez = 0;
        int p  = 0;

        float emb[8];
        int   mb[8];
#pragma unroll
        for (int u = 0; u < 8; u++) {
            int t = (dir == 0) ? (t0 + u) : (t1 - 1 - u);
            emb[u] = __expf(lg[(size_t)t * L_ + j]);
            mb[u]  = mk[t];
        }

        for (int blk = 0; blk < CSTEPS / 8; blk++) {
#pragma unroll
            for (int u = 0; u < 8; u++) {
                const int s = blk * 8 + u;
                float x = (dir == 0) ? A : A * emb[u];
                buf[p][j] = x;
                __syncwarp();
                const ulonglong2* bp = reinterpret_cast<const ulonglong2*>(buf[p]);
                unsigned long long a0 = 0ull, a1 = 0ull, a2 = 0ull, a3 = 0ull;
                ulonglong2 v00 = bp[0];
#pragma unroll
                for (int q = 0; q < 4; q++) {
                    ulonglong2 v0 = (q == 0) ? v00 : bp[q * 2];
                    ulonglong2 v1 = bp[q * 2 + 1];
                    a0 = ffma2(v0.x, etp[q * 4 + 0], a0);
                    a1 = ffma2(v0.y, etp[q * 4 + 1], a1);
                    a2 = ffma2(v1.x, etp[q * 4 + 2], a2);
                    a3 = ffma2(v1.y, etp[q * 4 + 3], a3);
                }
                float dot  = funpack_add(fadd2(fadd2(a0, a1), fadd2(a2, a3)));
                float Anew = (dir == 0) ? dot * emb[u] : dot;
                bool live  = (s < nlive);
                A = (mb[u] && live) ? Anew : A;

                if (u == 7) {
                    float a0f;
                    asm("mov.b64 {%0, _}, %1;" : "=f"(a0f) : "l"(v00.x));
                    a0f = fmaxf(a0f, 1e-30f);
                    int sb = (__float_as_int(a0f) >> 23) & 0xff;
                    A  *= __int_as_float((254 - sb) << 23);
                    ez += sb - 127;
                }
                p ^= 1;
                // prefetch: slot u serves step s+8 (time t0+s+8 fwd / t1-9-s bwd)
                // bounds: fwd <= 1920+63+8 = 1991 < S_; bwd >= 64-9 = 55 >= 0
                int tn = (dir == 0) ? (t0 + s + 8) : (t1 - 9 - s);
                emb[u] = __expf(lg[(size_t)tn * L_ + j]);
                mb[u]  = mk[tn];
            }
        }

        buf[p][j] = A;
        __syncwarp();
        float a0f = fmaxf(buf[p][0], 1e-30f);
        int   sb = (__float_as_int(a0f) >> 23) & 0xff;
        A  *= __int_as_float((254 - sb) << 23);
        ez += sb - 127;
        if (dir == 0) { g_av[b][c][j] = A; if (j == 0) g_aez[b][c] = ez; }
        else          { g_bv[b][c][j] = A; if (j == 0) g_bez[b][c] = ez; }
    } else {
        const int nb  = blockIdx.x - SCAN_BLOCKS;
        const int b   = nb >> 4;
        const int seg = nb & 15;
        const int*   lb = labels + (size_t)b * S_;
        const int*   mk = mask + (size_t)b * S_;
        const float* lg = logits + (size_t)b * S_ * L_;

        float part = 0.f;
        int   msum = 0;
        int   t    = seg * 128 + tid;
        msum += (mk[t] > 0);
        if (t >= 1 && mk[t] > 0) {
            int cur = lb[t], prev = lb[t - 1];
            part += lg[(size_t)t * L_ + cur] + trans[prev * L_ + cur];
        }
#pragma unroll
        for (int off = 16; off > 0; off >>= 1) {
            part += __shfl_xor_sync(0xffffffffu, part, off);
            msum += __shfl_xor_sync(0xffffffffu, msum, off);
        }
        if (lane == 0) { sp[w] = part; sm_[w] = msum; }
        __syncthreads();
        if (tid == 0) {
            float ps = 0.f; int ms = 0;
#pragma unroll
            for (int i = 0; i < 4; i++) { ps += sp[i]; ms += sm_[i]; }
            g_num_part[b][seg]  = ps;
            g_msum_part[b][seg] = ms;
        }
    }
}

// ---------------------------------------------------------------------------
// Kernel 3: parallel combine + last-block loss reduce (round-12 form).
// ---------------------------------------------------------------------------
#define NJOBF (2 * NCH - 3)   // 61

__global__ __launch_bounds__(1024) void final_kernel(
    const float* __restrict__ logits,
    const int*   __restrict__ labels,
    const float* __restrict__ start,
    const float* __restrict__ endt,
    float* __restrict__ loss_out)
{
    __shared__ double sh[64];
    __shared__ int is_last;
    const int b    = blockIdx.x;
    const int w    = threadIdx.x >> 5;
    const int lane = threadIdx.x & 31;

#pragma unroll
    for (int jj = 0; jj < 2; jj++) {
        int job = w + 32 * jj;
        if (job < NJOBF) {
            double val;
            if (job < NCH - 1) {
                int c = job;
                float d = g_av[b][c][lane] * g_bv[b][c + 1][lane];
#pragma unroll
                for (int off = 16; off > 0; off >>= 1)
                    d += __shfl_xor_sync(0xffffffffu, d, off);
                val = (double)__logf(d)
                    + (double)(g_aez[b][c] + g_bez[b][c + 1]) * LN2D;
            } else {
                int c = job - NCH + 2;
                float sm = g_bv[b][c][lane];
#pragma unroll
                for (int off = 16; off > 0; off >>= 1)
                    sm += __shfl_xor_sync(0xffffffffu, sm, off);
                val = -((double)__logf(sm) + (double)g_bez[b][c] * LN2D);
            }
            if (lane == 0) sh[job] = val;
        }
    }
    __syncthreads();

    if (w == 0) {
        double v = (lane < NJOBF) ? sh[lane] : 0.0;
        if (lane + 32 < NJOBF) v += sh[lane + 32];
#pragma unroll
        for (int off = 16; off > 0; off >>= 1)
            v += __shfl_xor_sync(0xffffffffu, v, off);
        if (lane == 0) {
            float part = 0.f; int m = 0;
#pragma unroll
            for (int i = 0; i < NSEG; i++) {
                part += g_num_part[b][i];
                m    += g_msum_part[b][i];
            }
            const int*   lb = labels + (size_t)b * S_;
            const float* lg = logits + (size_t)b * S_ * L_;
            int first = lb[0];
            int last  = lb[m - 1];
            float num = start[first] + lg[first] + part + endt[last];
            g_llh[b] = num - (float)v;
            __threadfence();
            int prev = atomicAdd(&g_done, 1);
            is_last = (prev == B_ - 1) ? 1 : 0;
        }
    }
    __syncthreads();

    if (is_last && w == 0) {
        __threadfence();
        float v = g_llh[lane];
#pragma unroll
        for (int off = 16; off > 0; off >>= 1)
            v += __shfl_xor_sync(0xffffffffu, v, off);
        if (lane == 0) {
            loss_out[0] = -(v * (1.0f / B_));
            g_done = 0;   // reset for next graph replay
            __threadfence();
        }
    }
}

// ---------------------------------------------------------------------------
extern "C" void kernel_launch(void* const* d_in, const int* in_sizes, int n_in,
                              void* d_out, int out_size)
{
    const float* hidden = (const float*)d_in[0];
    const float* W      = (const float*)d_in[1];
    const float* bias   = (const float*)d_in[2];
    const float* trans  = (const float*)d_in[3];
    const float* start  = (const float*)d_in[4];
    const float* endt   = (const float*)d_in[5];
    const int*   labels = (const int*)d_in[6];
    const int*   mask   = (const int*)d_in[7];

    float* out    = (float*)d_out;
    float* logits = out + 1;   // d_out = [loss, logits...]

    cudaFuncSetAttribute(gemm_mma_kernel, cudaFuncAttributeMaxDynamicSharedMemorySize, SMEM_TOTAL_G);

    wfrag_kernel<<<64, 256>>>(W);
    gemm_mma_kernel<<<(B_ * S_) / 64, 128, SMEM_TOTAL_G>>>(hidden, bias, logits);
    scannum_kernel<<<SCAN_BLOCKS + B_ * NSEG, 128>>>(logits, mask, trans, start, endt, labels);
    final_kernel<<<B_, 1024>>>(logits, labels, start, endt, out);
}

// round 16
// speedup vs baseline: 1.1490x; 1.0609x over previous
#include <cuda_runtime.h>
#include <cuda_bf16.h>
#include <cstdint>

#define B_ 32
#define S_ 2048
#define H_ 1024
#define L_ 32
#define NCH 32             // scan chunks per batch (64 steps each)
#define CSTEPS (S_ / NCH)  // 64
#define KC  32             // GEMM K-chunk
#define NKC (H_ / KC)      // 32 K-chunks
#define NSEG 16            // numerator segments
#define NPAIR (NCH - 1)    // 31 boundary pairs per batch
#define LN2D 0.6931471805599453

// scratch (no device allocs allowed)
__device__ double g_term[B_][NPAIR];     // +log(a_c . b_{c+1}) terms
__device__ double g_lsum[B_][NPAIR];     // -log(sum b_c) terms, c=1..30 at [c]
__device__ float g_num_part[B_][NSEG];
__device__ int   g_msum_part[B_][NSEG];
// W in mma.sync B-fragment order: [term(hi/lo)][kc][s][g][lane][reg] bf16x2
__device__ __align__(16) unsigned int g_Wf[2 * NKC * 512];

// ---- packed f32x2 helpers (scan) --------------------------------------------
__device__ __forceinline__ unsigned long long ffma2(unsigned long long a,
                                                    unsigned long long b,
                                                    unsigned long long c) {
    unsigned long long d;
    asm("fma.rn.f32x2 %0, %1, %2, %3;" : "=l"(d) : "l"(a), "l"(b), "l"(c));
    return d;
}
__device__ __forceinline__ unsigned long long fadd2(unsigned long long a,
                                                    unsigned long long b) {
    unsigned long long d;
    asm("add.rn.f32x2 %0, %1, %2;" : "=l"(d) : "l"(a), "l"(b));
    return d;
}
__device__ __forceinline__ unsigned long long fpack2(float lo, float hi) {
    unsigned long long d;
    asm("mov.b64 %0, {%1, %2};" : "=l"(d) : "f"(lo), "f"(hi));
    return d;
}
__device__ __forceinline__ float funpack_add(unsigned long long a) {
    float lo, hi;
    asm("mov.b64 {%0, %1}, %2;" : "=f"(lo), "=f"(hi) : "l"(a));
    return lo + hi;
}

// ---- cp.async ----------------------------------------------------------------
__device__ __forceinline__ void cp_async16(unsigned int dst, const void* src) {
    asm volatile("cp.async.cg.shared.global [%0], [%1], 16;" :: "r"(dst), "l"(src));
}
__device__ __forceinline__ void cp_commit() {
    asm volatile("cp.async.commit_group;");
}
template <int N>
__device__ __forceinline__ void cp_wait() {
    asm volatile("cp.async.wait_group %0;" :: "n"(N));
}

// ---- bf16 helpers -------------------------------------------------------------
__device__ __forceinline__ unsigned int bfpack(float x, float y) {
    unsigned int r;
    asm("cvt.rn.bf16x2.f32 %0, %1, %2;" : "=r"(r) : "f"(y), "f"(x));
    return r;
}
__device__ __forceinline__ void bfsplit(float x, float y,
                                        unsigned int& hi, unsigned int& lo) {
    unsigned int h = bfpack(x, y);
    float hx = __int_as_float(h << 16);
    float hy = __int_as_float(h & 0xffff0000u);
    hi = h;
    lo = bfpack(x - hx, y - hy);
}

// ---- mma.sync bf16 (m16n8k16, row.col, f32 acc) -------------------------------
__device__ __forceinline__ void mma_bf16(float* d, const unsigned int* a,
                                         const unsigned int* b) {
    asm volatile(
        "mma.sync.aligned.m16n8k16.row.col.f32.bf16.bf16.f32 "
        "{%0,%1,%2,%3}, {%4,%5,%6,%7}, {%8,%9}, {%0,%1,%2,%3};"
        : "+f"(d[0]), "+f"(d[1]), "+f"(d[2]), "+f"(d[3])
        : "r"(a[0]), "r"(a[1]), "r"(a[2]), "r"(a[3]), "r"(b[0]), "r"(b[1]));
}

// ---------------------------------------------------------------------------
// Kernel 0: W -> bf16 hi/lo B-fragments (KC=32), read-coalesced (r15 form).
// ---------------------------------------------------------------------------
__global__ void wfrag_kernel(const float* __restrict__ W) {
    int idx = blockIdx.x * blockDim.x + threadIdx.x;   // 0 .. 16383
    int n   = idx & 31;
    int kp  = idx >> 5;
    int k0  = kp * 2;
    float w0 = W[k0 * L_ + n];
    float w1 = W[(k0 + 1) * L_ + n];
    unsigned int hi, lo;
    bfsplit(w0, w1, hi, lo);
    int kc = k0 >> 5;
    int s  = (k0 >> 4) & 1;
    int r  = (k0 >> 3) & 1;
    int l  = (n & 7) * 4 + ((k0 >> 1) & 3);
    int g  = n >> 3;
    int base = ((((kc) * 2 + s) * 4 + g) * 32 + l) * 2 + r;
    g_Wf[base] = hi;
    g_Wf[base + NKC * 512] = lo;
}

// ---------------------------------------------------------------------------
// Kernel 1: logits = hidden @ W + b via mma.sync bf16-split (r12/r15 form).
// ---------------------------------------------------------------------------
#define HB_OFF 0u
#define WB_OFF 16384u
#define SMEM_TOTAL_G (16384 + 3 * 4096)

__global__ __launch_bounds__(128, 7) void gemm_mma_kernel(
    const float* __restrict__ hidden,
    const float* __restrict__ bias,
    float* __restrict__ out)
{
    extern __shared__ __align__(16) char smem[];
    const unsigned int sbase = (unsigned int)__cvta_generic_to_shared(smem);
    const int tid  = threadIdx.x;
    const int wid  = tid >> 5;
    const int lane = tid & 31;
    const size_t R0 = (size_t)blockIdx.x * 64;

    auto stageH = [&](int kc, int slot) {
#pragma unroll
        for (int p = 0; p < 4; p++) {
            int idx = p * 128 + tid;
            int row = idx >> 3;
            int c16 = idx & 7;
            const float* src = hidden + (R0 + row) * H_ + kc * KC + c16 * 4;
            unsigned int dst = sbase + HB_OFF + (unsigned int)slot * 8192u
                + (unsigned int)(row * 128 + (((c16 >> 1) ^ (row & 3)) << 5)
                                 + (c16 & 1) * 16);
            cp_async16(dst, src);
        }
    };
    auto stageW = [&](int kc, int slot) {
#pragma unroll
        for (int i = 0; i < 2; i++) {
            int idx = tid + 128 * i;
            int t   = idx >> 7;
            int off = idx & 127;
            const char* src = (const char*)g_Wf + (t * NKC + kc) * 2048 + off * 16;
            unsigned int dst = sbase + WB_OFF + (unsigned int)slot * 4096u
                + (unsigned int)(t * 2048 + off * 16);
            cp_async16(dst, src);
        }
    };

    float acc[4][4];
#pragma unroll
    for (int g = 0; g < 4; g++)
#pragma unroll
        for (int r = 0; r < 4; r++) acc[g][r] = 0.f;

    stageH(0, 0); stageW(0, 0); cp_commit();

    const int r0 = wid * 16 + (lane >> 2);
    const int r1 = r0 + 8;
    const int co = (lane & 3) * 2;

    for (int kc = 0; kc < NKC; kc++) {
        const int hs = kc & 1;
        const int wslot = kc % 3;
        if (kc + 1 < NKC) {
            stageH(kc + 1, hs ^ 1);
            stageW(kc + 1, (kc + 1) % 3);
            cp_commit();
            cp_wait<1>();
        } else {
            cp_wait<0>();
        }
        __syncthreads();

        const float* hb = (const float*)(smem + HB_OFF + hs * 8192);
        const unsigned int* wb = (const unsigned int*)(smem + WB_OFF + wslot * 4096);

#pragma unroll
        for (int s = 0; s < 2; s++) {
            const int cc0 = 2 * s, cc1 = 2 * s + 1;
            float2 p00 = *(const float2*)(hb + r0 * 32 + ((cc0 ^ (r0 & 3)) << 3) + co);
            float2 p10 = *(const float2*)(hb + r1 * 32 + ((cc0 ^ (r1 & 3)) << 3) + co);
            float2 p01 = *(const float2*)(hb + r0 * 32 + ((cc1 ^ (r0 & 3)) << 3) + co);
            float2 p11 = *(const float2*)(hb + r1 * 32 + ((cc1 ^ (r1 & 3)) << 3) + co);
            unsigned int ahi[4], alo[4];
            bfsplit(p00.x, p00.y, ahi[0], alo[0]);
            bfsplit(p10.x, p10.y, ahi[1], alo[1]);
            bfsplit(p01.x, p01.y, ahi[2], alo[2]);
            bfsplit(p11.x, p11.y, ahi[3], alo[3]);
#pragma unroll
            for (int g = 0; g < 4; g++) {
                uint2 bh = *(const uint2*)(wb + ((s * 4 + g) * 32 + lane) * 2);
                uint2 bl = *(const uint2*)(wb + 512 + ((s * 4 + g) * 32 + lane) * 2);
                unsigned int bhr[2] = { bh.x, bh.y };
                unsigned int blr[2] = { bl.x, bl.y };
                mma_bf16(acc[g], ahi, bhr);
                mma_bf16(acc[g], ahi, blr);
                mma_bf16(acc[g], alo, bhr);
            }
        }
        __syncthreads();
    }

#pragma unroll
    for (int g = 0; g < 4; g++) {
        int cbase = g * 8 + co;
        float b0 = bias[cbase];
        float b1 = bias[cbase + 1];
        float* p = out + (R0 + r0) * L_ + cbase;
        float* q = out + (R0 + r1) * L_ + cbase;
        p[0] = acc[g][0] + b0;
        p[1] = acc[g][1] + b1;
        q[0] = acc[g][2] + b0;
        q[1] = acc[g][3] + b1;
    }
}

// ---------------------------------------------------------------------------
// Kernel 2: fused chunk-scans (paired fwd/bwd) + numerator partials.
// Scan blocks: 2 boundary pairs per block. Global pair gp = blk*2 + (w>>1),
// b = gp/31, p = gp%31. Warp (w&1)==0: fwd chunk p; (w&1)==1: bwd chunk p+1.
// Block tail: pair computes boundary term (and bwd lsum) in-place.
// ---------------------------------------------------------------------------
#define SCAN_BLOCKS (B_ * NPAIR / 2)              // 496

__global__ __launch_bounds__(128) void scannum_kernel(
    const float* __restrict__ logits,
    const int*   __restrict__ mask,
    const float* __restrict__ trans,
    const float* __restrict__ start,
    const float* __restrict__ endt,
    const int*   __restrict__ labels)
{
    __shared__ __align__(16) float buf4[4][2][L_];
    __shared__ float exch[4][L_];
    __shared__ int   ezs[4];
    __shared__ float sp[4];
    __shared__ int   sm_[4];

    const int tid  = threadIdx.x;
    const int w    = tid >> 5;
    const int lane = tid & 31;

    if (blockIdx.x < SCAN_BLOCKS) {
        // ---- scan path ----
        const int gp  = blockIdx.x * 2 + (w >> 1);
        const int b   = gp / NPAIR;
        const int p_  = gp % NPAIR;
        const int dir = w & 1;                    // 0 = fwd chunk p_, 1 = bwd chunk p_+1
        const int c   = dir ? (p_ + 1) : p_;
        const int j   = lane;
        const float* lg = logits + (size_t)b * S_ * L_;
        const int*   mk = mask + (size_t)b * S_;
        float (*buf)[L_] = buf4[w];

        const int t0 = (c == 0) ? 1 : CSTEPS * c;
        const int t1 = CSTEPS * (c + 1);
        const int nlive = t1 - t0;

        unsigned long long etp[16];
        if (dir == 0) {
#pragma unroll
            for (int u = 0; u < 16; u++)
                etp[u] = fpack2(__expf(trans[(2 * u) * L_ + j]),
                                __expf(trans[(2 * u + 1) * L_ + j]));
        } else {
#pragma unroll
            for (int u = 0; u < 16; u++)
                etp[u] = fpack2(__expf(trans[j * L_ + 2 * u]),
                                __expf(trans[j * L_ + 2 * u + 1]));
        }

        float A;
        if (dir == 0) A = (c == 0)       ? __expf(start[j] + lg[j]) : 1.0f;
        else          A = (c == NCH - 1) ? __expf(endt[j])          : 1.0f;
        int ez = 0;
        int pb = 0;

        float emb[8];
        int   mb[8];
#pragma unroll
        for (int u = 0; u < 8; u++) {
            int t = (dir == 0) ? (t0 + u) : (t1 - 1 - u);
            emb[u] = __expf(lg[(size_t)t * L_ + j]);
            mb[u]  = mk[t];
        }

        for (int blk = 0; blk < CSTEPS / 8; blk++) {
#pragma unroll
            for (int u = 0; u < 8; u++) {
                const int s = blk * 8 + u;
                float x = (dir == 0) ? A : A * emb[u];
                buf[pb][j] = x;
                __syncwarp();
                const ulonglong2* bp = reinterpret_cast<const ulonglong2*>(buf[pb]);
                unsigned long long a0 = 0ull, a1 = 0ull, a2 = 0ull, a3 = 0ull;
                ulonglong2 v00 = bp[0];
#pragma unroll
                for (int q = 0; q < 4; q++) {
                    ulonglong2 v0 = (q == 0) ? v00 : bp[q * 2];
                    ulonglong2 v1 = bp[q * 2 + 1];
                    a0 = ffma2(v0.x, etp[q * 4 + 0], a0);
                    a1 = ffma2(v0.y, etp[q * 4 + 1], a1);
                    a2 = ffma2(v1.x, etp[q * 4 + 2], a2);
                    a3 = ffma2(v1.y, etp[q * 4 + 3], a3);
                }
                float dot  = funpack_add(fadd2(fadd2(a0, a1), fadd2(a2, a3)));
                float Anew = (dir == 0) ? dot * emb[u] : dot;
                bool live  = (s < nlive);
                A = (mb[u] && live) ? Anew : A;

                if (u == 7) {
                    float a0f;
                    asm("mov.b64 {%0, _}, %1;" : "=f"(a0f) : "l"(v00.x));
                    a0f = fmaxf(a0f, 1e-30f);
                    int sb = (__float_as_int(a0f) >> 23) & 0xff;
                    A  *= __int_as_float((254 - sb) << 23);
                    ez += sb - 127;
                }
                pb ^= 1;
                // prefetch: slot u serves step s+8; fwd <= 1991 < S_, bwd >= 55 >= 0
                int tn = (dir == 0) ? (t0 + s + 8) : (t1 - 9 - s);
                emb[u] = __expf(lg[(size_t)tn * L_ + j]);
                mb[u]  = mk[tn];
            }
        }

        // final power-of-two renorm
        buf[pb][j] = A;
        __syncwarp();
        float a0f = fmaxf(buf[pb][0], 1e-30f);
        int   sb = (__float_as_int(a0f) >> 23) & 0xff;
        A  *= __int_as_float((254 - sb) << 23);
        ez += sb - 127;

        // exchange post-renorm state across the pair
        exch[w][j] = A;
        if (j == 0) ezs[w] = ez;
        __syncthreads();

        if (dir == 0) {
            // boundary term: log(a_p . b_{p+1}) + (ezF + ezB) ln2
            float d = exch[w][j] * exch[w + 1][j];
#pragma unroll
            for (int off = 16; off > 0; off >>= 1)
                d += __shfl_xor_sync(0xffffffffu, d, off);
            if (j == 0)
                g_term[b][p_] = (double)__logf(d)
                              + (double)(ezs[w] + ezs[w + 1]) * LN2D;
        } else {
            // lsum term for bwd chunk c = p_+1 (needed for c = 1..NCH-2)
            if (c <= NCH - 2) {
                float sv = exch[w][j];
#pragma unroll
                for (int off = 16; off > 0; off >>= 1)
                    sv += __shfl_xor_sync(0xffffffffu, sv, off);
                if (j == 0)
                    g_lsum[b][c] = (double)__logf(sv) + (double)ezs[w] * LN2D;
            }
        }
    } else {
        // ---- numerator path ----
        const int nb  = blockIdx.x - SCAN_BLOCKS;
        const int b   = nb >> 4;
        const int seg = nb & 15;
        const int*   lb = labels + (size_t)b * S_;
        const int*   mk = mask + (size_t)b * S_;
        const float* lg = logits + (size_t)b * S_ * L_;

        float part = 0.f;
        int   msum = 0;
        int   t    = seg * 128 + tid;
        msum += (mk[t] > 0);
        if (t >= 1 && mk[t] > 0) {
            int cur = lb[t], prev = lb[t - 1];
            part += lg[(size_t)t * L_ + cur] + trans[prev * L_ + cur];
        }
#pragma unroll
        for (int off = 16; off > 0; off >>= 1) {
            part += __shfl_xor_sync(0xffffffffu, part, off);
            msum += __shfl_xor_sync(0xffffffffu, msum, off);
        }
        if (lane == 0) { sp[w] = part; sm_[w] = msum; }
        __syncthreads();
        if (tid == 0) {
            float ps = 0.f; int ms = 0;
#pragma unroll
            for (int i = 0; i < 4; i++) { ps += sp[i]; ms += sm_[i]; }
            g_num_part[b][seg]  = ps;
            g_msum_part[b][seg] = ms;
        }
    }
}

// ---------------------------------------------------------------------------
// Kernel 3: final — ONE block, warp b sums its 61 scalar terms + numerator.
// ---------------------------------------------------------------------------
__global__ __launch_bounds__(1024) void final_kernel(
    const float* __restrict__ logits,
    const int*   __restrict__ labels,
    const float* __restrict__ start,
    const float* __restrict__ endt,
    float* __restrict__ loss_out)
{
    __shared__ float sh[B_];
    const int b    = threadIdx.x >> 5;
    const int lane = threadIdx.x & 31;

    double v = 0.0;
    if (lane < NPAIR) v += g_term[b][lane];                      // +31 terms
    if (lane >= 1 && lane <= NCH - 2) v -= g_lsum[b][lane];      // -30 terms
#pragma unroll
    for (int off = 16; off > 0; off >>= 1)
        v += __shfl_xor_sync(0xffffffffu, v, off);

    if (lane == 0) {
        float part = 0.f; int m = 0;
#pragma unroll
        for (int i = 0; i < NSEG; i++) {
            part += g_num_part[b][i];
            m    += g_msum_part[b][i];
        }
        const int*   lb = labels + (size_t)b * S_;
        const float* lg = logits + (size_t)b * S_ * L_;
        int first = lb[0];
        int last  = lb[m - 1];
        float num = start[first] + lg[first] + part + endt[last];
        sh[b] = num - (float)v;
    }
    __syncthreads();
    if (threadIdx.x < 32) {
        float x = sh[threadIdx.x];
#pragma unroll
        for (int off = 16; off > 0; off >>= 1)
            x += __shfl_xor_sync(0xffffffffu, x, off);
        if (threadIdx.x == 0) loss_out[0] = -(x * (1.0f / B_));
    }
}

// ---------------------------------------------------------------------------
extern "C" void kernel_launch(void* const* d_in, const int* in_sizes, int n_in,
                              void* d_out, int out_size)
{
    const float* hidden = (const float*)d_in[0];
    const float* W      = (const float*)d_in[1];
    const float* bias   = (const float*)d_in[2];
    const float* trans  = (const float*)d_in[3];
    const float* start  = (const float*)d_in[4];
    const float* endt   = (const float*)d_in[5];
    const int*   labels = (const int*)d_in[6];
    const int*   mask   = (const int*)d_in[7];

    float* out    = (float*)d_out;
    float* logits = out + 1;   // d_out = [loss, logits...]

    cudaFuncSetAttribute(gemm_mma_kernel, cudaFuncAttributeMaxDynamicSharedMemorySize, SMEM_TOTAL_G);

    wfrag_kernel<<<64, 256>>>(W);
    gemm_mma_kernel<<<(B_ * S_) / 64, 128, SMEM_TOTAL_G>>>(hidden, bias, logits);
    scannum_kernel<<<SCAN_BLOCKS + B_ * NSEG, 128>>>(logits, mask, trans, start, endt, labels);
    final_kernel<<<1, B_ * 32>>>(logits, labels, start, endt, out);
}